// round 16
// baseline (speedup 1.0000x reference)
#include <cuda_runtime.h>
#include <cuda_bf16.h>
#include <cstdint>

// Problem constants (fixed by the dataset)
#define HEADS 4
#define DHEAD 32
#define CDIM  128
#define NTOT  147456          // 384*384
#define NT    64              // n-tile width, phase 1
#define NT2   128             // n-tile width, phase 2
#define NBLK  144             // persistent grid: 1 CTA/SM, co-resident (<=148)

// ---------------- scratch (static device globals) ----------------
__device__ float g_part[NBLK * 4096];          // per-block ctx partials [b][h][d][e]
__device__ float g_zpart[NBLK * 128];          // per-block z partials
__device__ float g_Mt[CDIM * CDIM];            // M transposed: g_Mt[c2][o]
__device__ float g_M2[CDIM * CDIM];
__device__ float g_b2[CDIM];
__device__ int g_bcount = 0;                   // barrier count (self-resetting)
__device__ int g_bsense = 0;                   // barrier sense (persists across replays)

// ---------------- portable primitives ----------------
__device__ __forceinline__ uint32_t smem_u32(const void* p) {
    uint32_t a;
    asm("{ .reg .u64 t; cvta.to.shared.u64 t, %1; cvt.u32.u64 %0, t; }" : "=r"(a) : "l"(p));
    return a;
}
#define LDM_X4(r0, r1, r2, r3, addr) \
    asm volatile("ldmatrix.sync.aligned.m8n8.x4.shared.b16 {%0,%1,%2,%3}, [%4];" \
                 : "=r"(r0), "=r"(r1), "=r"(r2), "=r"(r3) : "r"(addr))
#define LDM_X4_T(r0, r1, r2, r3, addr) \
    asm volatile("ldmatrix.sync.aligned.m8n8.x4.trans.shared.b16 {%0,%1,%2,%3}, [%4];" \
                 : "=r"(r0), "=r"(r1), "=r"(r2), "=r"(r3) : "r"(addr))
#define MMA16816(d, a0, a1, a2, a3, b0, b1) \
    asm volatile("mma.sync.aligned.m16n8k16.row.col.f32.bf16.bf16.f32 " \
                 "{%0,%1,%2,%3}, {%4,%5,%6,%7}, {%8,%9}, {%0,%1,%2,%3};" \
                 : "+f"((d)[0]), "+f"((d)[1]), "+f"((d)[2]), "+f"((d)[3]) \
                 : "r"(a0), "r"(a1), "r"(a2), "r"(a3), "r"(b0), "r"(b1))

__device__ __forceinline__ uint32_t pack_bf2(float a, float b) {
    __nv_bfloat162 t = __floats2bfloat162_rn(a, b);
    return *reinterpret_cast<uint32_t*>(&t);
}
__device__ __forceinline__ void split_pair(float a, float b, uint32_t& hi, uint32_t& lo) {
    __nv_bfloat16 ha = __float2bfloat16(a), hb = __float2bfloat16(b);
    hi = pack_bf2(__bfloat162float(ha), __bfloat162float(hb));
    lo = pack_bf2(a - __bfloat162float(ha), b - __bfloat162float(hb));
}

// smem geometry
#define LDA  136                       // A image row stride (bf16 elems)
#define CLD  72                        // phase-1 x/ek/v tile row stride
#define CLD2 136                       // phase-2 x tile row stride (128 cols + pad)
#define A_IMG (128 * LDA * 2)          // 34816 B
#define B_IMG (128 * CLD * 2)          // 18432 B
#define F_XBH (4 * A_IMG)
#define F_XBL (4 * A_IMG + B_IMG)
#define F_VH  (4 * A_IMG + 2 * B_IMG)
#define F_VL  (4 * A_IMG + 3 * B_IMG)
#define F_SMEM (4 * A_IMG + 4 * B_IMG)   // 212992
// phase 2 reuse: M2H at 0, M2L at A_IMG, BH/BL at F_XBH / F_XBH + A_IMG
#define P2_BH F_XBH
#define P2_BL (F_XBH + A_IMG)

// ---------------- THE mega-kernel ----------------
__global__ void __launch_bounds__(512, 1)
mega_kernel(const float* __restrict__ x, const float* __restrict__ w_qkv,
            const float* __restrict__ b_qkv, const float* __restrict__ w_out,
            const float* __restrict__ b_out, float* __restrict__ y,
            int N, int tpb1, int tpb2) {
    extern __shared__ __align__(16) char sm[];
    __shared__ float zbuf[128];
    __shared__ float cred[512];
    __shared__ float ctxrow[32];
    __shared__ float mr[128];
    const int tid = threadIdx.x, lane = tid & 31, w = tid >> 5;
    const int wm = w & 3, wn = w >> 2;
    const uint32_t uSM = smem_u32(sm);

    // barrier sense (thread 0 only uses it); read before any block can flip
    int sns = 0;
    if (tid == 0) sns = *(volatile int*)&g_bsense;

#define GRID_BAR() do { \
    __threadfence(); \
    __syncthreads(); \
    if (tid == 0) { \
        int tgt = sns ^ 1; \
        if (atomicAdd(&g_bcount, 1) == NBLK - 1) { \
            g_bcount = 0; \
            __threadfence(); \
            *(volatile int*)&g_bsense = tgt; \
        } else { \
            while (*(volatile int*)&g_bsense != tgt) { __nanosleep(64); } \
        } \
        sns = tgt; \
    } \
    __syncthreads(); \
} while (0)

    // ============ PHASE 1: k,v GEMM + exp + block-diagonal ctx partials ============
    const int chead = w & 3, cq = w >> 2;
    const int dhalf = cq & 1, ehalf = cq >> 1;

    // stage 4 weight images directly from w_qkv (fp32 -> bf16 hi/lo in-block)
    for (int i = tid; i < 8192; i += 512) {
        int r = i >> 5, q = i & 31;
        float4 v = *reinterpret_cast<const float4*>(w_qkv + (size_t)(128 + r) * 128 + q * 4);
        uint2 hp, lp;
        split_pair(v.x, v.y, hp.x, lp.x);
        split_pair(v.z, v.w, hp.y, lp.y);
        int set = r >> 7, rr = r & 127;
        *reinterpret_cast<uint2*>(sm + (set * 2 + 0) * A_IMG + (rr * LDA + q * 4) * 2) = hp;
        *reinterpret_cast<uint2*>(sm + (set * 2 + 1) * A_IMG + (rr * LDA + q * 4) * 2) = lp;
    }
    if (tid < 128) zbuf[tid] = 0.0f;

    float bk[4], bv[4];
    #pragma unroll
    for (int i = 0; i < 2; i++) {
        int r0 = wm * 32 + i * 16 + (lane >> 2);
        bk[2 * i] = b_qkv[128 + r0];      bk[2 * i + 1] = b_qkv[128 + r0 + 8];
        bv[2 * i] = b_qkv[256 + r0];      bv[2 * i + 1] = b_qkv[256 + r0 + 8];
    }

    float accc[2][4];
    #pragma unroll
    for (int j = 0; j < 2; j++)
        #pragma unroll
        for (int r = 0; r < 4; r++) accc[j][r] = 0.0f;
    float zth[4] = {0.f, 0.f, 0.f, 0.f};

    const uint32_t a_row = wm * 32 + (lane & 15);
    const uint32_t a_col = (lane >> 4) * 8;
    const uint32_t b_krow = (lane & 7) + ((lane >> 3) & 1) * 8;
    const uint32_t b_noff = ((lane >> 4) & 1) * 8;

    {
        int t = blockIdx.x;
        float4 pf[4];
        #pragma unroll
        for (int i = 0; i < 4; i++) {
            int idx = tid + i * 512, r = idx >> 4, q = idx & 15;
            pf[i] = *reinterpret_cast<const float4*>(x + (size_t)r * N + t * NT + q * 4);
        }
        __syncthreads();

        for (int it = 0; it < tpb1; it++, t += NBLK) {
            // stage x tile (hi/lo)
            #pragma unroll
            for (int i = 0; i < 4; i++) {
                int idx = tid + i * 512, r = idx >> 4, q = idx & 15;
                float4 v = pf[i];
                uint2 hp, lp;
                split_pair(v.x, v.y, hp.x, lp.x);
                split_pair(v.z, v.w, hp.y, lp.y);
                *reinterpret_cast<uint2*>(sm + F_XBH + (r * CLD + q * 4) * 2) = hp;
                *reinterpret_cast<uint2*>(sm + F_XBL + (r * CLD + q * 4) * 2) = lp;
            }
            __syncthreads();
            if (it + 1 < tpb1) {
                #pragma unroll
                for (int i = 0; i < 4; i++) {
                    int idx = tid + i * 512, r = idx >> 4, q = idx & 15;
                    pf[i] = *reinterpret_cast<const float4*>(
                        x + (size_t)r * N + (t + NBLK) * NT + q * 4);
                }
            }

            // fused k+v MMAs sharing one B-fragment load per ks
            float acck[2][2][4], accv[2][2][4];
            #pragma unroll
            for (int i = 0; i < 2; i++)
                #pragma unroll
                for (int j = 0; j < 2; j++)
                    #pragma unroll
                    for (int r = 0; r < 4; r++) { acck[i][j][r] = 0.0f; accv[i][j][r] = 0.0f; }

            #pragma unroll
            for (int ks = 0; ks < 8; ks++) {
                uint32_t bh[4], bl[4];
                {
                    uint32_t boff = ((ks * 16 + b_krow) * CLD + wn * 16 + b_noff) * 2;
                    LDM_X4_T(bh[0], bh[1], bh[2], bh[3], uSM + F_XBH + boff);
                    LDM_X4_T(bl[0], bl[1], bl[2], bl[3], uSM + F_XBL + boff);
                }
                #pragma unroll
                for (int i = 0; i < 2; i++) {
                    uint32_t off = ((a_row + i * 16) * LDA + ks * 16 + a_col) * 2;
                    uint32_t ah[4], al[4];
                    LDM_X4(ah[0], ah[1], ah[2], ah[3], uSM + 0 * A_IMG + off);
                    LDM_X4(al[0], al[1], al[2], al[3], uSM + 1 * A_IMG + off);
                    #pragma unroll
                    for (int j = 0; j < 2; j++) {
                        MMA16816(acck[i][j], ah[0], ah[1], ah[2], ah[3], bh[2*j], bh[2*j+1]);
                        MMA16816(acck[i][j], ah[0], ah[1], ah[2], ah[3], bl[2*j], bl[2*j+1]);
                        MMA16816(acck[i][j], al[0], al[1], al[2], al[3], bh[2*j], bh[2*j+1]);
                    }
                    LDM_X4(ah[0], ah[1], ah[2], ah[3], uSM + 2 * A_IMG + off);
                    LDM_X4(al[0], al[1], al[2], al[3], uSM + 3 * A_IMG + off);
                    #pragma unroll
                    for (int j = 0; j < 2; j++) {
                        MMA16816(accv[i][j], ah[0], ah[1], ah[2], ah[3], bh[2*j], bh[2*j+1]);
                        MMA16816(accv[i][j], ah[0], ah[1], ah[2], ah[3], bl[2*j], bl[2*j+1]);
                        MMA16816(accv[i][j], al[0], al[1], al[2], al[3], bh[2*j], bh[2*j+1]);
                    }
                }
            }
            __syncthreads();

            // write ek = exp(k+bias) into XB (hi/lo), v+bias into V; accumulate z
            #pragma unroll
            for (int i = 0; i < 2; i++) {
                const int r0 = wm * 32 + i * 16 + (lane >> 2), r1 = r0 + 8;
                #pragma unroll
                for (int j = 0; j < 2; j++) {
                    const int col = wn * 16 + j * 8 + (lane & 3) * 2;
                    float e00 = __expf(acck[i][j][0] + bk[2 * i]);
                    float e01 = __expf(acck[i][j][1] + bk[2 * i]);
                    float e10 = __expf(acck[i][j][2] + bk[2 * i + 1]);
                    float e11 = __expf(acck[i][j][3] + bk[2 * i + 1]);
                    zth[2 * i]     += e00 + e01;
                    zth[2 * i + 1] += e10 + e11;
                    uint32_t h0, l0, h1, l1;
                    split_pair(e00, e01, h0, l0);
                    split_pair(e10, e11, h1, l1);
                    *reinterpret_cast<uint32_t*>(sm + F_XBH + (r0 * CLD + col) * 2) = h0;
                    *reinterpret_cast<uint32_t*>(sm + F_XBL + (r0 * CLD + col) * 2) = l0;
                    *reinterpret_cast<uint32_t*>(sm + F_XBH + (r1 * CLD + col) * 2) = h1;
                    *reinterpret_cast<uint32_t*>(sm + F_XBL + (r1 * CLD + col) * 2) = l1;
                    float v00 = accv[i][j][0] + bv[2 * i];
                    float v01 = accv[i][j][1] + bv[2 * i];
                    float v10 = accv[i][j][2] + bv[2 * i + 1];
                    float v11 = accv[i][j][3] + bv[2 * i + 1];
                    split_pair(v00, v01, h0, l0);
                    split_pair(v10, v11, h1, l1);
                    *reinterpret_cast<uint32_t*>(sm + F_VH + (r0 * CLD + col) * 2) = h0;
                    *reinterpret_cast<uint32_t*>(sm + F_VL + (r0 * CLD + col) * 2) = l0;
                    *reinterpret_cast<uint32_t*>(sm + F_VH + (r1 * CLD + col) * 2) = h1;
                    *reinterpret_cast<uint32_t*>(sm + F_VL + (r1 * CLD + col) * 2) = l1;
                }
            }
            __syncthreads();

            // block-diagonal ctx MMA
            {
                const uint32_t arow = chead * 32 + dhalf * 16 + (lane & 15);
                const uint32_t erow = chead * 32 + ehalf * 16 + (lane & 15);
                const uint32_t ksub = (lane >> 4) * 8;
                #pragma unroll
                for (int ks = 0; ks < 4; ks++) {
                    uint32_t eh[4], el[4], vh4[4], vl4[4];
                    uint32_t aoff = (arow * CLD + ks * 16 + ksub) * 2;
                    uint32_t boff = (erow * CLD + ks * 16 + ksub) * 2;
                    LDM_X4(eh[0], eh[1], eh[2], eh[3], uSM + F_XBH + aoff);
                    LDM_X4(el[0], el[1], el[2], el[3], uSM + F_XBL + aoff);
                    LDM_X4(vh4[0], vh4[1], vh4[2], vh4[3], uSM + F_VH + boff);
                    LDM_X4(vl4[0], vl4[1], vl4[2], vl4[3], uSM + F_VL + boff);
                    #pragma unroll
                    for (int j = 0; j < 2; j++) {
                        MMA16816(accc[j], eh[0], eh[1], eh[2], eh[3], vh4[j], vh4[j + 2]);
                        MMA16816(accc[j], eh[0], eh[1], eh[2], eh[3], vl4[j], vl4[j + 2]);
                        MMA16816(accc[j], el[0], el[1], el[2], el[3], vh4[j], vh4[j + 2]);
                    }
                }
            }
            __syncthreads();
        }
    }

    // ---- write ctx + z partials ----
    {
        float* part = g_part + (size_t)blockIdx.x * 4096 + chead * 1024;
        const int dloc0 = dhalf * 16 + (lane >> 2);
        #pragma unroll
        for (int j = 0; j < 2; j++) {
            const int eloc = ehalf * 16 + j * 8 + (lane & 3) * 2;
            *reinterpret_cast<float2*>(part + dloc0 * 32 + eloc) =
                make_float2(accc[j][0], accc[j][1]);
            *reinterpret_cast<float2*>(part + (dloc0 + 8) * 32 + eloc) =
                make_float2(accc[j][2], accc[j][3]);
        }
    }
    #pragma unroll
    for (int c = 0; c < 4; c++) {
        zth[c] += __shfl_xor_sync(0xffffffffu, zth[c], 1);
        zth[c] += __shfl_xor_sync(0xffffffffu, zth[c], 2);
    }
    if ((lane & 3) == 0) {
        #pragma unroll
        for (int c = 0; c < 4; c++) {
            int row = wm * 32 + (c >> 1) * 16 + (lane >> 2) + (c & 1) * 8;
            atomicAdd(&zbuf[row], zth[c]);
        }
    }
    __syncthreads();
    if (tid < 128) g_zpart[blockIdx.x * 128 + tid] = zbuf[tid];

    GRID_BAR();

    // ============ COMPOSE stage A: blocks 0..127 -> ctx row b, z[b], M column b ============
    if (blockIdx.x < 128) {
        const int b = blockIdx.x;
        {
            int q = tid >> 5, e = tid & 31;
            float s = 0.0f;
            #pragma unroll
            for (int i2 = 0; i2 < 9; i2++)
                s += g_part[(size_t)(q * 9 + i2) * 4096 + b * 32 + e];
            cred[tid] = s;
        }
        __syncthreads();
        if (tid < 32) {
            float a2 = 0.0f;
            #pragma unroll
            for (int q2 = 0; q2 < 16; q2++) a2 += cred[q2 * 32 + tid];
            ctxrow[tid] = a2;
        }
        __syncthreads();
        cred[tid] = (tid < NBLK) ? g_zpart[tid * 128 + b] : 0.0f;
        __syncthreads();
        #pragma unroll
        for (int st = 256; st > 0; st >>= 1) {
            if (tid < st) cred[tid] += cred[tid + st];
            __syncthreads();
        }
        const float invz = 1.0f / cred[0];
        if (tid < 128) {
            const int hb = (b >> 5) * 32;
            const float* wr = w_out + tid * 128 + hb;
            float a = 0.0f;
            #pragma unroll
            for (int e = 0; e < 32; e++) a += wr[e] * ctxrow[e];
            g_Mt[b * 128 + tid] = a * invz;   // M[tid][b]
        }
    }

    GRID_BAR();

    // ============ COMPOSE stage B: blocks 0..127 -> M2 row o, b2[o] ============
    if (blockIdx.x < 128) {
        const int o = blockIdx.x;
        if (tid < 128) mr[tid] = g_Mt[tid * 128 + o];   // M row o
        __syncthreads();
        {
            int c = tid & 127, jc = tid >> 7;
            float a = 0.0f;
            #pragma unroll
            for (int j = 0; j < 32; j++)
                a += mr[jc * 32 + j] * w_qkv[(jc * 32 + j) * 128 + c];
            cred[tid] = a;
        }
        __syncthreads();
        if (tid < 128)
            g_M2[o * 128 + tid] = cred[tid] + cred[128 + tid] + cred[256 + tid] + cred[384 + tid];
        __syncthreads();
        cred[tid] = (tid < 128) ? mr[tid] * b_qkv[tid] : 0.0f;
        __syncthreads();
        #pragma unroll
        for (int st = 256; st > 0; st >>= 1) {
            if (tid < st) cred[tid] += cred[tid + st];
            __syncthreads();
        }
        if (tid == 0) g_b2[o] = cred[0] + b_out[o];
    }

    GRID_BAR();

    // ============ PHASE 2: y = M2 @ x + b2 (NT2=128 tiles; x is L2-hot) ============
    // stage M2 images (hi -> 0, lo -> A_IMG)
    for (int i = tid; i < 4096; i += 512) {
        int r = i >> 5, q = i & 31;
        float4 v = *reinterpret_cast<const float4*>(g_M2 + r * 128 + q * 4);
        uint2 hp, lp;
        split_pair(v.x, v.y, hp.x, lp.x);
        split_pair(v.z, v.w, hp.y, lp.y);
        *reinterpret_cast<uint2*>(sm + 0 * A_IMG + (r * LDA + q * 4) * 2) = hp;
        *reinterpret_cast<uint2*>(sm + 1 * A_IMG + (r * LDA + q * 4) * 2) = lp;
    }
    {
        int t = blockIdx.x;
        float4 pf[8];
        #pragma unroll
        for (int i = 0; i < 8; i++) {
            int idx = tid + i * 512, r = idx >> 5, q = idx & 31;
            pf[i] = *reinterpret_cast<const float4*>(x + (size_t)r * N + t * NT2 + q * 4);
        }
        __syncthreads();

        float b2r[4];
        #pragma unroll
        for (int i = 0; i < 2; i++) {
            int r0 = wm * 32 + i * 16 + (lane >> 2);
            b2r[2 * i] = g_b2[r0];  b2r[2 * i + 1] = g_b2[r0 + 8];
        }

        for (int it = 0; it < tpb2; it++, t += NBLK) {
            #pragma unroll
            for (int i = 0; i < 8; i++) {
                int idx = tid + i * 512, r = idx >> 5, q = idx & 31;
                float4 v = pf[i];
                uint2 hp, lp;
                split_pair(v.x, v.y, hp.x, lp.x);
                split_pair(v.z, v.w, hp.y, lp.y);
                *reinterpret_cast<uint2*>(sm + P2_BH + (r * CLD2 + q * 4) * 2) = hp;
                *reinterpret_cast<uint2*>(sm + P2_BL + (r * CLD2 + q * 4) * 2) = lp;
            }
            __syncthreads();
            if (it + 1 < tpb2) {
                #pragma unroll
                for (int i = 0; i < 8; i++) {
                    int idx = tid + i * 512, r = idx >> 5, q = idx & 31;
                    pf[i] = *reinterpret_cast<const float4*>(
                        x + (size_t)r * N + (t + NBLK) * NT2 + q * 4);
                }
            }

            float acc[2][4][4];
            #pragma unroll
            for (int i = 0; i < 2; i++)
                #pragma unroll
                for (int j = 0; j < 4; j++)
                    #pragma unroll
                    for (int r = 0; r < 4; r++) acc[i][j][r] = 0.0f;

            #pragma unroll
            for (int ks = 0; ks < 8; ks++) {
                uint32_t bh[2][4], bl[2][4];
                #pragma unroll
                for (int j2 = 0; j2 < 2; j2++) {
                    uint32_t boff = ((ks * 16 + b_krow) * CLD2 + wn * 32 + j2 * 16 + b_noff) * 2;
                    LDM_X4_T(bh[j2][0], bh[j2][1], bh[j2][2], bh[j2][3], uSM + P2_BH + boff);
                    LDM_X4_T(bl[j2][0], bl[j2][1], bl[j2][2], bl[j2][3], uSM + P2_BL + boff);
                }
                #pragma unroll
                for (int i = 0; i < 2; i++) {
                    uint32_t off = ((a_row + i * 16) * LDA + ks * 16 + a_col) * 2;
                    uint32_t ah[4], al[4];
                    LDM_X4(ah[0], ah[1], ah[2], ah[3], uSM + 0 * A_IMG + off);
                    LDM_X4(al[0], al[1], al[2], al[3], uSM + 1 * A_IMG + off);
                    #pragma unroll
                    for (int j = 0; j < 4; j++) {
                        const int j2 = j >> 1, q = (j & 1) * 2;
                        MMA16816(acc[i][j], ah[0], ah[1], ah[2], ah[3], bh[j2][q], bh[j2][q+1]);
                        MMA16816(acc[i][j], ah[0], ah[1], ah[2], ah[3], bl[j2][q], bl[j2][q+1]);
                        MMA16816(acc[i][j], al[0], al[1], al[2], al[3], bh[j2][q], bh[j2][q+1]);
                    }
                }
            }

            // epilogue
            #pragma unroll
            for (int i = 0; i < 2; i++) {
                const int row = wm * 32 + i * 16 + (lane >> 2);
                const float b0 = b2r[2 * i], b1 = b2r[2 * i + 1];
                #pragma unroll
                for (int j = 0; j < 4; j++) {
                    const int col = t * NT2 + wn * 32 + j * 8 + (lane & 3) * 2;
                    *reinterpret_cast<float2*>(y + (size_t)row * N + col) =
                        make_float2(acc[i][j][0] + b0, acc[i][j][1] + b0);
                    *reinterpret_cast<float2*>(y + (size_t)(row + 8) * N + col) =
                        make_float2(acc[i][j][2] + b1, acc[i][j][3] + b1);
                }
            }
            __syncthreads();
        }
    }
#undef GRID_BAR
}

// ---------------- launch ----------------
extern "C" void kernel_launch(void* const* d_in, const int* in_sizes, int n_in,
                              void* d_out, int out_size) {
    const float* x     = (const float*)d_in[0];
    const float* w_qkv = (const float*)d_in[1];
    const float* b_qkv = (const float*)d_in[2];
    const float* w_out = (const float*)d_in[3];
    const float* b_out = (const float*)d_in[4];
    float* y = (float*)d_out;

    const int N = in_sizes[0] / CDIM;          // 147456
    const int tpb1 = (N / NT) / NBLK;          // 16
    const int tpb2 = (N / NT2) / NBLK;         // 8

    cudaFuncSetAttribute(mega_kernel, cudaFuncAttributeMaxDynamicSharedMemorySize, F_SMEM);
    mega_kernel<<<NBLK, 512, F_SMEM>>>(x, w_qkv, b_qkv, w_out, b_out, y, N, tpb1, tpb2);
}

// round 17
// speedup vs baseline: 1.5072x; 1.5072x over previous
#include <cuda_runtime.h>
#include <cuda_bf16.h>
#include <cstdint>

// Problem constants (fixed by the dataset)
#define HEADS 4
#define DHEAD 32
#define CDIM  128
#define NTOT  147456          // 384*384
#define NT    64              // n-tile width
#define NBLK  144             // phase-1 grid: 1 CTA/SM, co-resident (<=148)
#define GRID_OUT 288          // out grid: 1 wave at 2 CTA/SM; tpb = 8

// ---------------- scratch (static device globals) ----------------
__device__ float g_part[NBLK * 4096];          // per-block ctx partials [b][h][d][e]
__device__ float g_zpart[NBLK * 128];          // per-block z partials
__device__ float g_Mt[CDIM * CDIM];            // M transposed: g_Mt[c2][o]
__device__ float g_M2[CDIM * CDIM];
__device__ float g_b2[CDIM];
__device__ int g_bcount = 0;                   // barrier count (self-resetting)
__device__ int g_bsense = 0;                   // barrier sense (persists across replays)

// ---------------- portable primitives ----------------
__device__ __forceinline__ uint32_t smem_u32(const void* p) {
    uint32_t a;
    asm("{ .reg .u64 t; cvta.to.shared.u64 t, %1; cvt.u32.u64 %0, t; }" : "=r"(a) : "l"(p));
    return a;
}
#define LDM_X4(r0, r1, r2, r3, addr) \
    asm volatile("ldmatrix.sync.aligned.m8n8.x4.shared.b16 {%0,%1,%2,%3}, [%4];" \
                 : "=r"(r0), "=r"(r1), "=r"(r2), "=r"(r3) : "r"(addr))
#define LDM_X4_T(r0, r1, r2, r3, addr) \
    asm volatile("ldmatrix.sync.aligned.m8n8.x4.trans.shared.b16 {%0,%1,%2,%3}, [%4];" \
                 : "=r"(r0), "=r"(r1), "=r"(r2), "=r"(r3) : "r"(addr))
#define MMA16816(d, a0, a1, a2, a3, b0, b1) \
    asm volatile("mma.sync.aligned.m16n8k16.row.col.f32.bf16.bf16.f32 " \
                 "{%0,%1,%2,%3}, {%4,%5,%6,%7}, {%8,%9}, {%0,%1,%2,%3};" \
                 : "+f"((d)[0]), "+f"((d)[1]), "+f"((d)[2]), "+f"((d)[3]) \
                 : "r"(a0), "r"(a1), "r"(a2), "r"(a3), "r"(b0), "r"(b1))

__device__ __forceinline__ uint32_t pack_bf2(float a, float b) {
    __nv_bfloat162 t = __floats2bfloat162_rn(a, b);
    return *reinterpret_cast<uint32_t*>(&t);
}
__device__ __forceinline__ void split_pair(float a, float b, uint32_t& hi, uint32_t& lo) {
    __nv_bfloat16 ha = __float2bfloat16(a), hb = __float2bfloat16(b);
    hi = pack_bf2(__bfloat162float(ha), __bfloat162float(hb));
    lo = pack_bf2(a - __bfloat162float(ha), b - __bfloat162float(hb));
}

// smem geometry
#define LDA  136                       // A image row stride (bf16 elems)
#define CLD  72                        // x/ek/v tile row stride (bf16 elems)
#define A_IMG (128 * LDA * 2)          // 34816 B
#define B_IMG (128 * CLD * 2)          // 18432 B
#define F_XBH (4 * A_IMG)
#define F_XBL (4 * A_IMG + B_IMG)
#define F_VH  (4 * A_IMG + 2 * B_IMG)
#define F_VL  (4 * A_IMG + 3 * B_IMG)
#define F_SMEM (4 * A_IMG + 4 * B_IMG)   // 212992
#define OUT_BH (2 * A_IMG)
#define OUT_BL (2 * A_IMG + B_IMG)
#define OUT_SMEM (2 * A_IMG + 2 * B_IMG)  // 106496

// ---------------- kernel 1: kv GEMM + exp + ctx partials + full compose ----------------
__global__ void __launch_bounds__(512, 1)
gemm_kv_ctx_compose(const float* __restrict__ x, const float* __restrict__ w_qkv,
                    const float* __restrict__ b_qkv, const float* __restrict__ w_out,
                    const float* __restrict__ b_out, int N, int tpb) {
    extern __shared__ __align__(16) char sm[];
    __shared__ float zbuf[128];
    __shared__ float cred[512];
    __shared__ float ctxrow[32];
    __shared__ float mr[128];
    const int tid = threadIdx.x, lane = tid & 31, w = tid >> 5;
    const int wm = w & 3, wn = w >> 2;
    const uint32_t uSM = smem_u32(sm);

    int sns = 0;
    if (tid == 0) sns = *(volatile int*)&g_bsense;

#define GRID_BAR() do { \
    __threadfence(); \
    __syncthreads(); \
    if (tid == 0) { \
        int tgt = sns ^ 1; \
        if (atomicAdd(&g_bcount, 1) == NBLK - 1) { \
            g_bcount = 0; \
            __threadfence(); \
            *(volatile int*)&g_bsense = tgt; \
        } else { \
            while (*(volatile int*)&g_bsense != tgt) { __nanosleep(64); } \
        } \
        sns = tgt; \
    } \
    __syncthreads(); \
} while (0)

    // ============ PHASE 1: k,v GEMM + exp + block-diagonal ctx partials ============
    const int chead = w & 3, cq = w >> 2;
    const int dhalf = cq & 1, ehalf = cq >> 1;

    for (int i = tid; i < 8192; i += 512) {
        int r = i >> 5, q = i & 31;
        float4 v = *reinterpret_cast<const float4*>(w_qkv + (size_t)(128 + r) * 128 + q * 4);
        uint2 hp, lp;
        split_pair(v.x, v.y, hp.x, lp.x);
        split_pair(v.z, v.w, hp.y, lp.y);
        int set = r >> 7, rr = r & 127;
        *reinterpret_cast<uint2*>(sm + (set * 2 + 0) * A_IMG + (rr * LDA + q * 4) * 2) = hp;
        *reinterpret_cast<uint2*>(sm + (set * 2 + 1) * A_IMG + (rr * LDA + q * 4) * 2) = lp;
    }
    if (tid < 128) zbuf[tid] = 0.0f;

    float bk[4], bv[4];
    #pragma unroll
    for (int i = 0; i < 2; i++) {
        int r0 = wm * 32 + i * 16 + (lane >> 2);
        bk[2 * i] = b_qkv[128 + r0];      bk[2 * i + 1] = b_qkv[128 + r0 + 8];
        bv[2 * i] = b_qkv[256 + r0];      bv[2 * i + 1] = b_qkv[256 + r0 + 8];
    }

    float accc[2][4];
    #pragma unroll
    for (int j = 0; j < 2; j++)
        #pragma unroll
        for (int r = 0; r < 4; r++) accc[j][r] = 0.0f;
    float zth[4] = {0.f, 0.f, 0.f, 0.f};

    const uint32_t a_row = wm * 32 + (lane & 15);
    const uint32_t a_col = (lane >> 4) * 8;
    const uint32_t b_krow = (lane & 7) + ((lane >> 3) & 1) * 8;
    const uint32_t b_noff = ((lane >> 4) & 1) * 8;

    {
        int t = blockIdx.x;
        float4 pf[4];
        #pragma unroll
        for (int i = 0; i < 4; i++) {
            int idx = tid + i * 512, r = idx >> 4, q = idx & 15;
            pf[i] = *reinterpret_cast<const float4*>(x + (size_t)r * N + t * NT + q * 4);
        }
        __syncthreads();

        for (int it = 0; it < tpb; it++, t += NBLK) {
            #pragma unroll
            for (int i = 0; i < 4; i++) {
                int idx = tid + i * 512, r = idx >> 4, q = idx & 15;
                float4 v = pf[i];
                uint2 hp, lp;
                split_pair(v.x, v.y, hp.x, lp.x);
                split_pair(v.z, v.w, hp.y, lp.y);
                *reinterpret_cast<uint2*>(sm + F_XBH + (r * CLD + q * 4) * 2) = hp;
                *reinterpret_cast<uint2*>(sm + F_XBL + (r * CLD + q * 4) * 2) = lp;
            }
            __syncthreads();
            if (it + 1 < tpb) {
                #pragma unroll
                for (int i = 0; i < 4; i++) {
                    int idx = tid + i * 512, r = idx >> 4, q = idx & 15;
                    pf[i] = *reinterpret_cast<const float4*>(
                        x + (size_t)r * N + (t + NBLK) * NT + q * 4);
                }
            }

            float acck[2][2][4], accv[2][2][4];
            #pragma unroll
            for (int i = 0; i < 2; i++)
                #pragma unroll
                for (int j = 0; j < 2; j++)
                    #pragma unroll
                    for (int r = 0; r < 4; r++) { acck[i][j][r] = 0.0f; accv[i][j][r] = 0.0f; }

            #pragma unroll
            for (int ks = 0; ks < 8; ks++) {
                uint32_t bh[4], bl[4];
                {
                    uint32_t boff = ((ks * 16 + b_krow) * CLD + wn * 16 + b_noff) * 2;
                    LDM_X4_T(bh[0], bh[1], bh[2], bh[3], uSM + F_XBH + boff);
                    LDM_X4_T(bl[0], bl[1], bl[2], bl[3], uSM + F_XBL + boff);
                }
                #pragma unroll
                for (int i = 0; i < 2; i++) {
                    uint32_t off = ((a_row + i * 16) * LDA + ks * 16 + a_col) * 2;
                    uint32_t ah[4], al[4];
                    LDM_X4(ah[0], ah[1], ah[2], ah[3], uSM + 0 * A_IMG + off);
                    LDM_X4(al[0], al[1], al[2], al[3], uSM + 1 * A_IMG + off);
                    #pragma unroll
                    for (int j = 0; j < 2; j++) {
                        MMA16816(acck[i][j], ah[0], ah[1], ah[2], ah[3], bh[2*j], bh[2*j+1]);
                        MMA16816(acck[i][j], ah[0], ah[1], ah[2], ah[3], bl[2*j], bl[2*j+1]);
                        MMA16816(acck[i][j], al[0], al[1], al[2], al[3], bh[2*j], bh[2*j+1]);
                    }
                    LDM_X4(ah[0], ah[1], ah[2], ah[3], uSM + 2 * A_IMG + off);
                    LDM_X4(al[0], al[1], al[2], al[3], uSM + 3 * A_IMG + off);
                    #pragma unroll
                    for (int j = 0; j < 2; j++) {
                        MMA16816(accv[i][j], ah[0], ah[1], ah[2], ah[3], bh[2*j], bh[2*j+1]);
                        MMA16816(accv[i][j], ah[0], ah[1], ah[2], ah[3], bl[2*j], bl[2*j+1]);
                        MMA16816(accv[i][j], al[0], al[1], al[2], al[3], bh[2*j], bh[2*j+1]);
                    }
                }
            }
            __syncthreads();

            #pragma unroll
            for (int i = 0; i < 2; i++) {
                const int r0 = wm * 32 + i * 16 + (lane >> 2), r1 = r0 + 8;
                #pragma unroll
                for (int j = 0; j < 2; j++) {
                    const int col = wn * 16 + j * 8 + (lane & 3) * 2;
                    float e00 = __expf(acck[i][j][0] + bk[2 * i]);
                    float e01 = __expf(acck[i][j][1] + bk[2 * i]);
                    float e10 = __expf(acck[i][j][2] + bk[2 * i + 1]);
                    float e11 = __expf(acck[i][j][3] + bk[2 * i + 1]);
                    zth[2 * i]     += e00 + e01;
                    zth[2 * i + 1] += e10 + e11;
                    uint32_t h0, l0, h1, l1;
                    split_pair(e00, e01, h0, l0);
                    split_pair(e10, e11, h1, l1);
                    *reinterpret_cast<uint32_t*>(sm + F_XBH + (r0 * CLD + col) * 2) = h0;
                    *reinterpret_cast<uint32_t*>(sm + F_XBL + (r0 * CLD + col) * 2) = l0;
                    *reinterpret_cast<uint32_t*>(sm + F_XBH + (r1 * CLD + col) * 2) = h1;
                    *reinterpret_cast<uint32_t*>(sm + F_XBL + (r1 * CLD + col) * 2) = l1;
                    float v00 = accv[i][j][0] + bv[2 * i];
                    float v01 = accv[i][j][1] + bv[2 * i];
                    float v10 = accv[i][j][2] + bv[2 * i + 1];
                    float v11 = accv[i][j][3] + bv[2 * i + 1];
                    split_pair(v00, v01, h0, l0);
                    split_pair(v10, v11, h1, l1);
                    *reinterpret_cast<uint32_t*>(sm + F_VH + (r0 * CLD + col) * 2) = h0;
                    *reinterpret_cast<uint32_t*>(sm + F_VL + (r0 * CLD + col) * 2) = l0;
                    *reinterpret_cast<uint32_t*>(sm + F_VH + (r1 * CLD + col) * 2) = h1;
                    *reinterpret_cast<uint32_t*>(sm + F_VL + (r1 * CLD + col) * 2) = l1;
                }
            }
            __syncthreads();

            {
                const uint32_t arow = chead * 32 + dhalf * 16 + (lane & 15);
                const uint32_t erow = chead * 32 + ehalf * 16 + (lane & 15);
                const uint32_t ksub = (lane >> 4) * 8;
                #pragma unroll
                for (int ks = 0; ks < 4; ks++) {
                    uint32_t eh[4], el[4], vh4[4], vl4[4];
                    uint32_t aoff = (arow * CLD + ks * 16 + ksub) * 2;
                    uint32_t boff = (erow * CLD + ks * 16 + ksub) * 2;
                    LDM_X4(eh[0], eh[1], eh[2], eh[3], uSM + F_XBH + aoff);
                    LDM_X4(el[0], el[1], el[2], el[3], uSM + F_XBL + aoff);
                    LDM_X4(vh4[0], vh4[1], vh4[2], vh4[3], uSM + F_VH + boff);
                    LDM_X4(vl4[0], vl4[1], vl4[2], vl4[3], uSM + F_VL + boff);
                    #pragma unroll
                    for (int j = 0; j < 2; j++) {
                        MMA16816(accc[j], eh[0], eh[1], eh[2], eh[3], vh4[j], vh4[j + 2]);
                        MMA16816(accc[j], eh[0], eh[1], eh[2], eh[3], vl4[j], vl4[j + 2]);
                        MMA16816(accc[j], el[0], el[1], el[2], el[3], vh4[j], vh4[j + 2]);
                    }
                }
            }
            __syncthreads();
        }
    }

    // ---- write ctx + z partials ----
    {
        float* part = g_part + (size_t)blockIdx.x * 4096 + chead * 1024;
        const int dloc0 = dhalf * 16 + (lane >> 2);
        #pragma unroll
        for (int j = 0; j < 2; j++) {
            const int eloc = ehalf * 16 + j * 8 + (lane & 3) * 2;
            *reinterpret_cast<float2*>(part + dloc0 * 32 + eloc) =
                make_float2(accc[j][0], accc[j][1]);
            *reinterpret_cast<float2*>(part + (dloc0 + 8) * 32 + eloc) =
                make_float2(accc[j][2], accc[j][3]);
        }
    }
    #pragma unroll
    for (int c = 0; c < 4; c++) {
        zth[c] += __shfl_xor_sync(0xffffffffu, zth[c], 1);
        zth[c] += __shfl_xor_sync(0xffffffffu, zth[c], 2);
    }
    if ((lane & 3) == 0) {
        #pragma unroll
        for (int c = 0; c < 4; c++) {
            int row = wm * 32 + (c >> 1) * 16 + (lane >> 2) + (c & 1) * 8;
            atomicAdd(&zbuf[row], zth[c]);
        }
    }
    __syncthreads();
    if (tid < 128) g_zpart[blockIdx.x * 128 + tid] = zbuf[tid];

    GRID_BAR();

    // ============ COMPOSE stage A: blocks 0..127 -> ctx row b, z[b], M column b ============
    if (blockIdx.x < 128) {
        const int b = blockIdx.x;
        {
            int q = tid >> 5, e = tid & 31;
            float s = 0.0f;
            #pragma unroll
            for (int i2 = 0; i2 < 9; i2++)
                s += g_part[(size_t)(q * 9 + i2) * 4096 + b * 32 + e];
            cred[tid] = s;
        }
        __syncthreads();
        if (tid < 32) {
            float a2 = 0.0f;
            #pragma unroll
            for (int q2 = 0; q2 < 16; q2++) a2 += cred[q2 * 32 + tid];
            ctxrow[tid] = a2;
        }
        __syncthreads();
        cred[tid] = (tid < NBLK) ? g_zpart[tid * 128 + b] : 0.0f;
        __syncthreads();
        #pragma unroll
        for (int st = 256; st > 0; st >>= 1) {
            if (tid < st) cred[tid] += cred[tid + st];
            __syncthreads();
        }
        const float invz = 1.0f / cred[0];
        if (tid < 128) {
            const int hb = (b >> 5) * 32;
            const float* wr = w_out + tid * 128 + hb;
            float a = 0.0f;
            #pragma unroll
            for (int e = 0; e < 32; e++) a += wr[e] * ctxrow[e];
            g_Mt[b * 128 + tid] = a * invz;   // M[tid][b]
        }
    }

    GRID_BAR();

    // ============ COMPOSE stage B: blocks 0..127 -> M2 row o, b2[o] ============
    if (blockIdx.x < 128) {
        const int o = blockIdx.x;
        if (tid < 128) mr[tid] = g_Mt[tid * 128 + o];   // M row o
        __syncthreads();
        {
            int c = tid & 127, jc = tid >> 7;
            float a = 0.0f;
            #pragma unroll
            for (int j = 0; j < 32; j++)
                a += mr[jc * 32 + j] * w_qkv[(jc * 32 + j) * 128 + c];
            cred[tid] = a;
        }
        __syncthreads();
        if (tid < 128)
            g_M2[o * 128 + tid] = cred[tid] + cred[128 + tid] + cred[256 + tid] + cred[384 + tid];
        __syncthreads();
        cred[tid] = (tid < 128) ? mr[tid] * b_qkv[tid] : 0.0f;
        __syncthreads();
        #pragma unroll
        for (int st = 256; st > 0; st >>= 1) {
            if (tid < st) cred[tid] += cred[tid + st];
            __syncthreads();
        }
        if (tid == 0) g_b2[o] = cred[0] + b_out[o];
    }
#undef GRID_BAR
}

// ---------------- HMMA accumulate over staged smem (generic 128x64 tile) ----------------
__device__ __forceinline__ void mma_tile_acc(
    uint32_t uSM, uint32_t offAh, uint32_t offAl, uint32_t offBh, uint32_t offBl,
    int lane, int wm, int wn, float acc[2][2][4])
{
    #pragma unroll
    for (int i = 0; i < 2; i++)
        #pragma unroll
        for (int j = 0; j < 2; j++)
            #pragma unroll
            for (int r = 0; r < 4; r++) acc[i][j][r] = 0.0f;

    const uint32_t a_row = wm * 32 + (lane & 15);
    const uint32_t a_col = (lane >> 4) * 8;
    const uint32_t b_krow = (lane & 7) + ((lane >> 3) & 1) * 8;
    const uint32_t b_noff = ((lane >> 4) & 1) * 8;

    #pragma unroll
    for (int ks = 0; ks < 8; ks++) {
        uint32_t ah[2][4], al[2][4], bh[4], bl[4];
        #pragma unroll
        for (int i = 0; i < 2; i++) {
            uint32_t off = ((a_row + i * 16) * LDA + ks * 16 + a_col) * 2;
            LDM_X4(ah[i][0], ah[i][1], ah[i][2], ah[i][3], uSM + offAh + off);
            LDM_X4(al[i][0], al[i][1], al[i][2], al[i][3], uSM + offAl + off);
        }
        {
            uint32_t boff = ((ks * 16 + b_krow) * CLD + wn * 16 + b_noff) * 2;
            LDM_X4_T(bh[0], bh[1], bh[2], bh[3], uSM + offBh + boff);
            LDM_X4_T(bl[0], bl[1], bl[2], bl[3], uSM + offBl + boff);
        }
        #pragma unroll
        for (int i = 0; i < 2; i++)
            #pragma unroll
            for (int j = 0; j < 2; j++) {
                MMA16816(acc[i][j], ah[i][0], ah[i][1], ah[i][2], ah[i][3], bh[2*j], bh[2*j+1]);
                MMA16816(acc[i][j], ah[i][0], ah[i][1], ah[i][2], ah[i][3], bl[2*j], bl[2*j+1]);
                MMA16816(acc[i][j], al[i][0], al[i][1], al[i][2], al[i][3], bh[2*j], bh[2*j+1]);
            }
    }
}

// load x tile [128c][64n] fp32 into 4 float4 regs (512 threads)
__device__ __forceinline__ void ldg_tile(float4 pf[4], const float* __restrict__ x,
                                         int N, int n0, int tid) {
    #pragma unroll
    for (int i = 0; i < 4; i++) {
        int idx = tid + i * 512, r = idx >> 4, q = idx & 15;
        pf[i] = *reinterpret_cast<const float4*>(x + (size_t)r * N + n0 + q * 4);
    }
}
__device__ __forceinline__ void sts_convert(const float4 pf[4], char* sm,
                                            uint32_t offBh, uint32_t offBl, int tid) {
    #pragma unroll
    for (int i = 0; i < 4; i++) {
        int idx = tid + i * 512, r = idx >> 4, q = idx & 15;
        float4 v = pf[i];
        uint2 hp, lp;
        split_pair(v.x, v.y, hp.x, lp.x);
        split_pair(v.z, v.w, hp.y, lp.y);
        *reinterpret_cast<uint2*>(sm + offBh + (r * CLD + q * 4) * 2) = hp;
        *reinterpret_cast<uint2*>(sm + offBl + (r * CLD + q * 4) * 2) = lp;
    }
}

// ---------------- kernel 2: y = M2 @ x + b2 (occ 2) ----------------
__global__ void __launch_bounds__(512, 2)
gemm_out_tc(const float* __restrict__ x, float* __restrict__ y, int N, int tpb) {
    extern __shared__ __align__(16) char sm[];
    const int tid = threadIdx.x, lane = tid & 31, w = tid >> 5;
    const int wm = w & 3, wn = w >> 2;
    const uint32_t uSM = smem_u32(sm);

    for (int i = tid; i < 4096; i += 512) {
        int r = i >> 5, q = i & 31;
        float4 v = *reinterpret_cast<const float4*>(g_M2 + r * 128 + q * 4);
        uint2 hp, lp;
        split_pair(v.x, v.y, hp.x, lp.x);
        split_pair(v.z, v.w, hp.y, lp.y);
        *reinterpret_cast<uint2*>(sm + 0 * A_IMG + (r * LDA + q * 4) * 2) = hp;
        *reinterpret_cast<uint2*>(sm + 1 * A_IMG + (r * LDA + q * 4) * 2) = lp;
    }

    int t = blockIdx.x;
    float4 pf[4];
    ldg_tile(pf, x, N, t * NT, tid);
    __syncthreads();

    for (int it = 0; it < tpb; it++, t += GRID_OUT) {
        sts_convert(pf, sm, OUT_BH, OUT_BL, tid);
        __syncthreads();
        if (it + 1 < tpb) ldg_tile(pf, x, N, (t + GRID_OUT) * NT, tid);

        float acc[2][2][4];
        mma_tile_acc(uSM, 0, A_IMG, OUT_BH, OUT_BL, lane, wm, wn, acc);
        // epilogue
        #pragma unroll
        for (int i = 0; i < 2; i++) {
            const int row = wm * 32 + i * 16 + (lane >> 2);
            const float b0 = g_b2[row], b1 = g_b2[row + 8];
            #pragma unroll
            for (int j = 0; j < 2; j++) {
                const int col = t * NT + wn * 16 + j * 8 + (lane & 3) * 2;
                *reinterpret_cast<float2*>(y + (size_t)row * N + col) =
                    make_float2(acc[i][j][0] + b0, acc[i][j][1] + b0);
                *reinterpret_cast<float2*>(y + (size_t)(row + 8) * N + col) =
                    make_float2(acc[i][j][2] + b1, acc[i][j][3] + b1);
            }
        }
        __syncthreads();
    }
}

// ---------------- launch ----------------
extern "C" void kernel_launch(void* const* d_in, const int* in_sizes, int n_in,
                              void* d_out, int out_size) {
    const float* x     = (const float*)d_in[0];
    const float* w_qkv = (const float*)d_in[1];
    const float* b_qkv = (const float*)d_in[2];
    const float* w_out = (const float*)d_in[3];
    const float* b_out = (const float*)d_in[4];
    float* y = (float*)d_out;

    const int N = in_sizes[0] / CDIM;          // 147456
    const int tpb1 = (N / NT) / NBLK;          // 16
    const int tpb2 = (N / NT) / GRID_OUT;      // 8

    cudaFuncSetAttribute(gemm_kv_ctx_compose, cudaFuncAttributeMaxDynamicSharedMemorySize, F_SMEM);
    cudaFuncSetAttribute(gemm_out_tc, cudaFuncAttributeMaxDynamicSharedMemorySize, OUT_SMEM);

    // 1) fused: k,v projection + exp + ctx partials + compose (M, M2, b2) via grid barriers
    gemm_kv_ctx_compose<<<NBLK, 512, F_SMEM>>>(x, w_qkv, b_qkv, w_out, b_out, N, tpb1);

    // 2) y = M2 @ x + b2
    gemm_out_tc<<<GRID_OUT, 512, OUT_SMEM>>>(x, y, N, tpb2);
}